// round 7
// baseline (speedup 1.0000x reference)
#include <cuda_runtime.h>

#define NQ  6
#define NL  3
#define TPB 128
// 2 rows per thread = 3 float4 in / 3 float4 out. Tan-form rotations with
// scale deferred into mixing constants and final magnitude.

__device__ __forceinline__ float sqrt_approx(float x) {
    float r; asm("sqrt.approx.f32 %0, %1;" : "=f"(r) : "f"(x)); return r;
}

// smem constant layout (floats, 16B-aligned groups):
//  [0..5]   th0[q] = rp[0][q][0] * 0.5      (entry-phase fold of layer-0 rot)
//  [8..13]  r1[q]  = tan(rp[1][q][0]*0.5)   (layer-1 rotation)
//  [16..21] r2[q]  = tan(rp[2][q][0]*0.5)   (layer-2 rotation)
//  [24..29] lam2[q] = (c1[q]*c2[q])^2       (deferred scale, squared)
//  [32+l*16 + 2k]   A[l][k] = 1 - t'        (t' = sigmoid(ep)/2)
//  [32+l*16 + 2k+1] B[l][k] = t' * mu[k+1]/mu[k]
//  [32+l*16 + 10]   BL[l]   = t'_4 * mu[4]/mu[5]
#define SMC 80

__global__ void __launch_bounds__(TPB, 12)
qc_fused(const float4* __restrict__ x4, float4* __restrict__ o4,
         const float* __restrict__ rp, const float* __restrict__ ep,
         int n_threads) {
    __shared__ __align__(16) float sC[SMC];

    int tid = threadIdx.x;
    if (tid == 0) {
#pragma unroll
        for (int i = 0; i < SMC; i++) sC[i] = 0.0f;
        float c1[NQ], c2[NQ];
#pragma unroll
        for (int q = 0; q < NQ; q++) {
            sC[q] = __ldg(&rp[q * 3]) * 0.5f;                       // th0
            float s, c;
            __sincosf(__ldg(&rp[(NQ + q) * 3]) * 0.5f, &s, &c);
            c1[q] = c; sC[8 + q] = __fdividef(s, c);                // r1
            __sincosf(__ldg(&rp[(2 * NQ + q) * 3]) * 0.5f, &s, &c);
            c2[q] = c; sC[16 + q] = __fdividef(s, c);               // r2
            float m = c1[q] * c2[q];
            sC[24 + q] = m * m;                                     // lam2
        }
#pragma unroll
        for (int l = 0; l < NL; l++) {
            float mu[NQ];
#pragma unroll
            for (int q = 0; q < NQ; q++)
                mu[q] = (l == 0) ? 1.0f : (l == 1 ? c1[q] : c1[q] * c2[q]);
            int base = 32 + l * 16;
#pragma unroll
            for (int k = 0; k < NQ - 1; k++) {
                float tp = 0.5f / (1.0f + __expf(-__ldg(&ep[l * 5 + k])));
                sC[base + 2 * k]     = 1.0f - tp;                   // A
                sC[base + 2 * k + 1] = tp * __fdividef(mu[k + 1], mu[k]); // B
                if (k == 4)
                    sC[base + 10] = tp * __fdividef(mu[4], mu[5]);  // BL
            }
        }
    }
    __syncthreads();

    int t0 = blockIdx.x * TPB + tid;
    if (t0 >= n_threads) return;
    int base = t0 * 3;

    float4 v0 = __ldcs(x4 + base);
    float4 v1 = __ldcs(x4 + base + 1);
    float4 v2 = __ldcs(x4 + base + 2);

    const float PIH = 1.57079632679489662f;
    float sr[12], si[12];
    {
        float4 ta = *(const float4*)(sC + 0);
        float4 tb = *(const float4*)(sC + 4);
        float th[6] = {ta.x, ta.y, ta.z, ta.w, tb.x, tb.y};
        float in[12] = {v0.x, v0.y, v0.z, v0.w, v1.x, v1.y,
                        v1.z, v1.w, v2.x, v2.y, v2.z, v2.w};
#pragma unroll
        for (int i = 0; i < 12; i++) {
            float ang = fmaf(in[i], PIH, -th[i % NQ]);
            __sincosf(ang, &si[i], &sr[i]);   // real=cos, imag=sin (scale 1)
        }
    }

#pragma unroll
    for (int l = 0; l < NL; l++) {
        if (l > 0) {
            // tan-form rotation (scaled state): nr = sr + r*si ; ni = si - r*sr
            float4 ra = *(const float4*)(sC + (l == 1 ? 8 : 16));
            float4 rb = *(const float4*)(sC + (l == 1 ? 12 : 20));
            float rr[6] = {ra.x, ra.y, ra.z, ra.w, rb.x, rb.y};
#pragma unroll
            for (int q = 0; q < NQ; q++) {
#pragma unroll
                for (int r = 0; r < 2; r++) {
                    int i = r * 6 + q;
                    float nr = fmaf( rr[q], si[i], sr[i]);
                    float ni = fmaf(-rr[q], sr[i], si[i]);
                    sr[i] = nr; si[i] = ni;
                }
            }
        }
        // mixing with scale-ratio-folded constants
        float4 m0 = *(const float4*)(sC + 32 + l * 16);
        float4 m1 = *(const float4*)(sC + 36 + l * 16);
        float4 m2 = *(const float4*)(sC + 40 + l * 16);
        float A[5] = {m0.x, m0.z, m1.x, m1.z, m2.x};
        float B[5] = {m0.y, m0.w, m1.y, m1.w, m2.y};
        float BL = m2.z;
        float old4a = sr[4], old4b = sr[10];
#pragma unroll
        for (int k = 0; k < NQ - 1; k++) {
            sr[k]     = fmaf(A[k], sr[k],     B[k] * sr[k + 1]);
            sr[6 + k] = fmaf(A[k], sr[6 + k], B[k] * sr[7 + k]);
        }
        sr[5]  = fmaf(A[4], sr[5],  BL * old4a);
        sr[11] = fmaf(A[4], sr[11], BL * old4b);
    }

    // magnitude with deferred scale: out = sqrt(lam2 * (sr^2 + si^2))
    float o[12];
    {
        float4 la = *(const float4*)(sC + 24);
        float4 lb = *(const float4*)(sC + 28);
        float lam[6] = {la.x, la.y, la.z, la.w, lb.x, lb.y};
#pragma unroll
        for (int i = 0; i < 12; i++) {
            float h = fmaf(sr[i], sr[i], si[i] * si[i]);
            o[i] = sqrt_approx(h * lam[i % NQ]);
        }
    }

    __stcs(o4 + base,     make_float4(o[0], o[1], o[2],  o[3]));
    __stcs(o4 + base + 1, make_float4(o[4], o[5], o[6],  o[7]));
    __stcs(o4 + base + 2, make_float4(o[8], o[9], o[10], o[11]));
}

extern "C" void kernel_launch(void* const* d_in, const int* in_sizes, int n_in,
                              void* d_out, int out_size) {
    const float* x  = (const float*)d_in[0];  // (BATCH, 6) fp32
    const float* rp = (const float*)d_in[1];  // (3, 6, 3) fp32
    const float* ep = (const float*)d_in[2];  // (3, 5)    fp32
    float* out = (float*)d_out;

    int total_f   = in_sizes[0];              // BATCH * 6
    int n_threads = total_f / 12;              // 2 rows per thread
    int blocks    = (n_threads + TPB - 1) / TPB;

    qc_fused<<<blocks, TPB>>>((const float4*)x, (float4*)out, rp, ep, n_threads);
}

// round 8
// speedup vs baseline: 1.2673x; 1.2673x over previous
#include <cuda_runtime.h>

#define NQ  6
#define NL  3
#define TPB 128
// 2 rows per thread = 3 float4 in / 3 float4 out. Tan-form rotations with
// scale deferred into mixing constants and final magnitude. Parallel prologue.

__device__ __forceinline__ float sqrt_approx(float x) {
    float r; asm("sqrt.approx.f32 %0, %1;" : "=f"(r) : "f"(x)); return r;
}

// smem constant layout (floats, 16B-aligned groups):
//  [0..5]   th0[q] = rp[0][q][0] * 0.5
//  [8..13]  r1[q]  = tan(rp[1][q][0]*0.5)
//  [16..21] r2[q]  = tan(rp[2][q][0]*0.5)
//  [24..29] lam2[q] = (c1[q]*c2[q])^2
//  [32+l*16 + 2k]   A[l][k] = 1 - t'       (t' = sigmoid(ep)/2)
//  [32+l*16 + 2k+1] B[l][k] = t' * mu[k+1]/mu[k]
//  [32+l*16 + 10]   BL[l]   = t' * mu[4]/mu[5]
#define SMC 80

__global__ void __launch_bounds__(TPB, 12)
qc_fused(const float4* __restrict__ x4, float4* __restrict__ o4,
         const float* __restrict__ rp, const float* __restrict__ ep,
         int n_threads) {
    __shared__ __align__(16) float sC[SMC];
    __shared__ float sCc[2 * NQ];      // scratch: c1[q], c2[q]

    int tid = threadIdx.x;
    // ---- prologue phase 1 (parallel) ----
    if (tid < 12) {                    // layers 1,2 rotations: c and tan
        int l = tid / NQ, q = tid % NQ;
        float s, c;
        __sincosf(__ldg(&rp[((l + 1) * NQ + q) * 3]) * 0.5f, &s, &c);
        sCc[l * NQ + q] = c;
        sC[8 + l * 8 + q] = __fdividef(s, c);          // r1 / r2
    } else if (tid < 18) {
        int q = tid - 12;
        sC[q] = __ldg(&rp[q * 3]) * 0.5f;              // th0
    } else if (tid >= 32 && tid < 32 + NL * 16) {      // zero-pad A/B region
        sC[tid] = 0.0f;
    }
    __syncthreads();
    // ---- prologue phase 2 (parallel) ----
    if (tid < NQ) {
        float m = sCc[tid] * sCc[NQ + tid];
        sC[24 + tid] = m * m;                          // lam2
    } else if (tid < NQ + NL * (NQ - 1)) {             // 6..20
        int k5 = tid - NQ;
        int l = k5 / 5, k = k5 % 5;
        float mu_k, mu_k1;
        if (l == 0)      { mu_k = 1.0f;                     mu_k1 = 1.0f; }
        else if (l == 1) { mu_k = sCc[k];                   mu_k1 = sCc[k + 1]; }
        else             { mu_k = sCc[k] * sCc[NQ + k];     mu_k1 = sCc[k + 1] * sCc[NQ + k + 1]; }
        float tp = 0.5f / (1.0f + __expf(-__ldg(&ep[l * 5 + k])));
        sC[32 + l * 16 + 2 * k]     = 1.0f - tp;            // A
        sC[32 + l * 16 + 2 * k + 1] = tp * __fdividef(mu_k1, mu_k);   // B
        if (k == 4)
            sC[32 + l * 16 + 10] = tp * __fdividef(mu_k, mu_k1);      // BL
    }
    __syncthreads();

    int t0 = blockIdx.x * TPB + tid;
    if (t0 >= n_threads) return;
    int base = t0 * 3;

    float4 v0 = __ldcs(x4 + base);
    float4 v1 = __ldcs(x4 + base + 1);
    float4 v2 = __ldcs(x4 + base + 2);

    const float PIH = 1.57079632679489662f;
    float sr[12], si[12];
    {
        float4 ta = *(const float4*)(sC + 0);
        float4 tb = *(const float4*)(sC + 4);
        float th[6] = {ta.x, ta.y, ta.z, ta.w, tb.x, tb.y};
        float in[12] = {v0.x, v0.y, v0.z, v0.w, v1.x, v1.y,
                        v1.z, v1.w, v2.x, v2.y, v2.z, v2.w};
#pragma unroll
        for (int i = 0; i < 12; i++) {
            float ang = fmaf(in[i], PIH, -th[i % NQ]);
            __sincosf(ang, &si[i], &sr[i]);   // real=cos, imag=sin (unit scale)
        }
    }

#pragma unroll
    for (int l = 0; l < NL; l++) {
        if (l > 0) {
            // tan-form rotation: nr = sr + r*si ; ni = si - r*sr
            float4 ra = *(const float4*)(sC + (l == 1 ? 8 : 16));
            float4 rb = *(const float4*)(sC + (l == 1 ? 12 : 20));
            float rr[6] = {ra.x, ra.y, ra.z, ra.w, rb.x, rb.y};
#pragma unroll
            for (int q = 0; q < NQ; q++) {
#pragma unroll
                for (int r = 0; r < 2; r++) {
                    int i = r * 6 + q;
                    float nr = fmaf( rr[q], si[i], sr[i]);
                    float ni = fmaf(-rr[q], sr[i], si[i]);
                    sr[i] = nr; si[i] = ni;
                }
            }
        }
        // mixing with scale-ratio-folded constants
        float4 m0 = *(const float4*)(sC + 32 + l * 16);
        float4 m1 = *(const float4*)(sC + 36 + l * 16);
        float4 m2 = *(const float4*)(sC + 40 + l * 16);
        float A[5] = {m0.x, m0.z, m1.x, m1.z, m2.x};
        float B[5] = {m0.y, m0.w, m1.y, m1.w, m2.y};
        float BL = m2.z;
        float old4a = sr[4], old4b = sr[10];
#pragma unroll
        for (int k = 0; k < NQ - 1; k++) {
            sr[k]     = fmaf(A[k], sr[k],     B[k] * sr[k + 1]);
            sr[6 + k] = fmaf(A[k], sr[6 + k], B[k] * sr[7 + k]);
        }
        sr[5]  = fmaf(A[4], sr[5],  BL * old4a);
        sr[11] = fmaf(A[4], sr[11], BL * old4b);
    }

    // magnitude with deferred scale: out = sqrt(lam2 * (sr^2 + si^2))
    float o[12];
    {
        float4 la = *(const float4*)(sC + 24);
        float4 lb = *(const float4*)(sC + 28);
        float lam[6] = {la.x, la.y, la.z, la.w, lb.x, lb.y};
#pragma unroll
        for (int i = 0; i < 12; i++) {
            float h = fmaf(sr[i], sr[i], si[i] * si[i]);
            o[i] = sqrt_approx(h * lam[i % NQ]);
        }
    }

    __stcs(o4 + base,     make_float4(o[0], o[1], o[2],  o[3]));
    __stcs(o4 + base + 1, make_float4(o[4], o[5], o[6],  o[7]));
    __stcs(o4 + base + 2, make_float4(o[8], o[9], o[10], o[11]));
}

extern "C" void kernel_launch(void* const* d_in, const int* in_sizes, int n_in,
                              void* d_out, int out_size) {
    const float* x  = (const float*)d_in[0];  // (BATCH, 6) fp32
    const float* rp = (const float*)d_in[1];  // (3, 6, 3) fp32
    const float* ep = (const float*)d_in[2];  // (3, 5)    fp32
    float* out = (float*)d_out;

    int total_f   = in_sizes[0];              // BATCH * 6
    int n_threads = total_f / 12;             // 2 rows per thread
    int blocks    = (n_threads + TPB - 1) / TPB;

    qc_fused<<<blocks, TPB>>>((const float4*)x, (float4*)out, rp, ep, n_threads);
}

// round 9
// speedup vs baseline: 1.3368x; 1.0548x over previous
#include <cuda_runtime.h>

#define NQ  6
#define NL  3
#define TPB 128
// 2 rows per thread = 3 float4 in / 3 float4 out. R5 body, occupancy cap 14.

__device__ __forceinline__ float sqrt_approx(float x) {
    float r; asm("sqrt.approx.f32 %0, %1;" : "=f"(r) : "f"(x)); return r;
}

__global__ void __launch_bounds__(TPB, 14)
qc_fused(const float4* __restrict__ x4, float4* __restrict__ o4,
         const float* __restrict__ rp, const float* __restrict__ ep,
         int n_threads) {
    // sTh0[q]      = rx[0][q]*0.5            (layer-0 rotation folded into entry phase)
    // sCS[l-1][q]  = (cos(rx/2), sin(rx/2))  for layers 1,2
    // sTT[l][k]    = (1-t, t), t = sigmoid(ep)/2
    __shared__ float  sTh0[NQ];
    __shared__ float2 sCS[(NL - 1) * NQ];
    __shared__ float2 sTT[NL * (NQ - 1)];

    int tid = threadIdx.x;
    if (tid < NL * NQ) {
        float rx = __ldg(&rp[tid * 3]) * 0.5f;
        if (tid < NQ) {
            sTh0[tid] = rx;
        } else {
            float s, c;
            __sincosf(rx, &s, &c);
            sCS[tid - NQ] = make_float2(c, s);
        }
    } else if (tid < NL * NQ + NL * (NQ - 1)) {
        int k = tid - NL * NQ;
        float t = 0.5f / (1.0f + __expf(-__ldg(&ep[k])));
        sTT[k] = make_float2(1.0f - t, t);
    }
    __syncthreads();

    int t0 = blockIdx.x * TPB + tid;
    if (t0 >= n_threads) return;
    int base = t0 * 3;                    // 3 float4 per thread

    float4 v0 = __ldcs(x4 + base);
    float4 v1 = __ldcs(x4 + base + 1);
    float4 v2 = __ldcs(x4 + base + 2);

    const float PIH = 1.57079632679489662f;
    float sr[12], si[12];
    // entry + layer-0 rotation fused: state = e^{i(x*pi/2 - th0_q)}
    // consume float4 lanes directly (no staging array -> lower reg pressure)
    __sincosf(fmaf(v0.x, PIH, -sTh0[0]), &si[0],  &sr[0]);
    __sincosf(fmaf(v0.y, PIH, -sTh0[1]), &si[1],  &sr[1]);
    __sincosf(fmaf(v0.z, PIH, -sTh0[2]), &si[2],  &sr[2]);
    __sincosf(fmaf(v0.w, PIH, -sTh0[3]), &si[3],  &sr[3]);
    __sincosf(fmaf(v1.x, PIH, -sTh0[4]), &si[4],  &sr[4]);
    __sincosf(fmaf(v1.y, PIH, -sTh0[5]), &si[5],  &sr[5]);
    __sincosf(fmaf(v1.z, PIH, -sTh0[0]), &si[6],  &sr[6]);
    __sincosf(fmaf(v1.w, PIH, -sTh0[1]), &si[7],  &sr[7]);
    __sincosf(fmaf(v2.x, PIH, -sTh0[2]), &si[8],  &sr[8]);
    __sincosf(fmaf(v2.y, PIH, -sTh0[3]), &si[9],  &sr[9]);
    __sincosf(fmaf(v2.z, PIH, -sTh0[4]), &si[10], &sr[10]);
    __sincosf(fmaf(v2.w, PIH, -sTh0[5]), &si[11], &sr[11]);

#pragma unroll
    for (int l = 0; l < NL; l++) {
        if (l > 0) {
            // rotation: nr = c*sr + s*si ; ni = c*si - s*sr
#pragma unroll
            for (int q = 0; q < NQ; q++) {
                float2 cs = sCS[(l - 1) * NQ + q];
#pragma unroll
                for (int r = 0; r < 2; r++) {
                    int i = r * 6 + q;
                    float nr = fmaf(cs.x, sr[i],  cs.y * si[i]);
                    float ni = fmaf(cs.x, si[i], -cs.y * sr[i]);
                    sr[i] = nr; si[i] = ni;
                }
            }
        }
        // mixing: new[k] = (1-t)*sr[k] + t*sr_old[k+1]
        float old4a = sr[4], old4b = sr[10];
#pragma unroll
        for (int k = 0; k < NQ - 1; k++) {
            float2 tt = sTT[l * 5 + k];
            sr[k]     = fmaf(tt.x, sr[k],     tt.y * sr[k + 1]);
            sr[6 + k] = fmaf(tt.x, sr[6 + k], tt.y * sr[7 + k]);
        }
        {
            float2 tt = sTT[l * 5 + 4];
            sr[5]  = fmaf(tt.x, sr[5],  tt.y * old4a);
            sr[11] = fmaf(tt.x, sr[11], tt.y * old4b);
        }
    }

    // magnitude: sqrt(sr^2 + si^2); write back into the v registers to keep
    // the live set small, then store.
    v0.x = sqrt_approx(fmaf(sr[0],  sr[0],  si[0]  * si[0]));
    v0.y = sqrt_approx(fmaf(sr[1],  sr[1],  si[1]  * si[1]));
    v0.z = sqrt_approx(fmaf(sr[2],  sr[2],  si[2]  * si[2]));
    v0.w = sqrt_approx(fmaf(sr[3],  sr[3],  si[3]  * si[3]));
    v1.x = sqrt_approx(fmaf(sr[4],  sr[4],  si[4]  * si[4]));
    v1.y = sqrt_approx(fmaf(sr[5],  sr[5],  si[5]  * si[5]));
    v1.z = sqrt_approx(fmaf(sr[6],  sr[6],  si[6]  * si[6]));
    v1.w = sqrt_approx(fmaf(sr[7],  sr[7],  si[7]  * si[7]));
    v2.x = sqrt_approx(fmaf(sr[8],  sr[8],  si[8]  * si[8]));
    v2.y = sqrt_approx(fmaf(sr[9],  sr[9],  si[9]  * si[9]));
    v2.z = sqrt_approx(fmaf(sr[10], sr[10], si[10] * si[10]));
    v2.w = sqrt_approx(fmaf(sr[11], sr[11], si[11] * si[11]));

    __stcs(o4 + base,     v0);
    __stcs(o4 + base + 1, v1);
    __stcs(o4 + base + 2, v2);
}

extern "C" void kernel_launch(void* const* d_in, const int* in_sizes, int n_in,
                              void* d_out, int out_size) {
    const float* x  = (const float*)d_in[0];  // (BATCH, 6) fp32
    const float* rp = (const float*)d_in[1];  // (3, 6, 3) fp32
    const float* ep = (const float*)d_in[2];  // (3, 5)    fp32
    float* out = (float*)d_out;

    int total_f   = in_sizes[0];              // BATCH * 6
    int n_threads = total_f / 12;             // 2 rows per thread
    int blocks    = (n_threads + TPB - 1) / TPB;

    qc_fused<<<blocks, TPB>>>((const float4*)x, (float4*)out, rp, ep, n_threads);
}